// round 11
// baseline (speedup 1.0000x reference)
#include <cuda_runtime.h>
#include <stdint.h>

#define NN 100000
#define EE 3200000
#define TT 8
#define FF 64
#define INIT_BLKS 391           // ceil(NN/256)

// ---------------- device scratch (allocation-free) ----------------
__device__ float g_y[(size_t)TT * NN * FF];   // 204.8 MB: y[t*N+n][f]
__device__ float g_h1[(size_t)NN * FF];       // 25.6 MB
__device__ float g_V1[64 * 512];              // permuted W1: V[fin][t*64+fout]
__device__ float g_V2[64 * 512];
__device__ int   g_pack[EE];                  // t*NN + src (payload)
__device__ int   g_edst[EE];                  // dst (sort key)
__device__ int   g_sedge[EE];                 // payload sorted by dst
__device__ int   g_cnt[NN];
__device__ int   g_off[NN];
__device__ int   g_kcur[NN];
__device__ int   g_total;
__device__ int   g_mode;                      // 1 = int64 indices, 0 = int32

#define FMA2(acc, a, b) asm("fma.rn.f32x2 %0, %1, %2, %0;" : "+l"(acc) : "l"(a), "l"(b))

// ---------------- init: mode detect + zero counters + permute W1/W2 --------
__global__ void __launch_bounds__(256) k_init(const int* __restrict__ ei,
                                              const float* __restrict__ W1,
                                              const float* __restrict__ W2) {
    int i = blockIdx.x * 256 + threadIdx.x;
    if (i < NN) g_cnt[i] = 0;
    if (i == 0) g_total = 0;

    if (i < 32768) {
        int fin = i >> 9;
        int j   = i & 511;
        int t   = j >> 6;
        int fo  = j & 63;
        g_V1[i] = W1[((t << 6) + fin) * 64 + fo];
        g_V2[i] = W2[((t << 6) + fin) * 64 + fo];
    }

    if (blockIdx.x == 0) {
        int v = ei[2 * threadIdx.x + 1];
        unsigned int ball = __ballot_sync(0xffffffffu, v != 0);
        __shared__ int nz[8];
        if ((threadIdx.x & 31) == 0) nz[threadIdx.x >> 5] = (ball != 0);
        __syncthreads();
        if (threadIdx.x == 0) {
            int any = 0;
            for (int w = 0; w < 8; w++) any |= nz[w];
            g_mode = any ? 0 : 1;
        }
    }
}

// ---------------- y[t*N+n][:] = in[n][:] @ W_t  (f32x2 packed FMA) ----------
__global__ void __launch_bounds__(128) k_gemm(const float* __restrict__ in,
                                              const float* __restrict__ V,
                                              float* __restrict__ y) {
    __shared__ float xs[16][64];
    int tid = threadIdx.x;
    int nb  = blockIdx.x * 16;

    {
        const float4* inv = (const float4*)(in + (size_t)nb * 64);
        float4* xsv = (float4*)&xs[0][0];
        xsv[tid]       = inv[tid];
        xsv[tid + 128] = inv[tid + 128];
    }
    __syncthreads();

    int jt = tid & 31;
    int ng = tid >> 5;

    unsigned long long acc[4][4][2];
#pragma unroll
    for (int i = 0; i < 4; i++)
#pragma unroll
        for (int s = 0; s < 4; s++) { acc[i][s][0] = 0ull; acc[i][s][1] = 0ull; }

    const ulonglong2* Vr = (const ulonglong2*)V;

#pragma unroll 4
    for (int fin = 0; fin < 64; ++fin) {
        unsigned long long xv[4];
#pragma unroll
        for (int i = 0; i < 4; i++) {
            unsigned int xb = __float_as_uint(xs[(ng << 2) + i][fin]);
            asm("mov.b64 %0, {%1, %1};" : "=l"(xv[i]) : "r"(xb));
        }
#pragma unroll
        for (int s = 0; s < 4; s++) {
            ulonglong2 w = __ldg(&Vr[fin * 128 + jt + s * 32]);
#pragma unroll
            for (int i = 0; i < 4; i++) {
                FMA2(acc[i][s][0], xv[i], w.x);
                FMA2(acc[i][s][1], xv[i], w.y);
            }
        }
    }

    ulonglong2* yv = (ulonglong2*)y;
#pragma unroll
    for (int s = 0; s < 4; s++) {
        int j4 = jt + s * 32;
        int t  = j4 >> 4;
        int c4 = j4 & 15;
#pragma unroll
        for (int i = 0; i < 4; i++) {
            int node = nb + (ng << 2) + i;
            ulonglong2 o;
            o.x = acc[i][s][0];
            o.y = acc[i][s][1];
            yv[(size_t)(t * NN + node) * 16 + c4] = o;
        }
    }
}

// ---------------- histogram over dst (caches key & payload) ----------------
__global__ void k_hist(const void* __restrict__ ei_raw, const void* __restrict__ ti_raw) {
    int e = blockIdx.x * 256 + threadIdx.x;
    if (e >= EE) return;
    int src, dst, t;
    if (g_mode) {
        const long long* ei = (const long long*)ei_raw;
        const long long* ti = (const long long*)ti_raw;
        src = (int)ei[e];
        dst = (int)ei[(size_t)EE + e];
        t   = (int)ti[e];
    } else {
        const int* ei = (const int*)ei_raw;
        const int* ti = (const int*)ti_raw;
        src = ei[e];
        dst = ei[EE + e];
        t   = ti[e];
    }
    g_pack[e] = t * NN + src;
    g_edst[e] = dst;
    atomicAdd(&g_cnt[dst], 1);
}

// ---------------- single-kernel ticketed scan ----------------
__global__ void __launch_bounds__(256) k_scanA(void) {
    __shared__ int sh[256];
    __shared__ int sbase;
    int i = blockIdx.x * 256 + threadIdx.x;
    int tid = threadIdx.x;
    int v = (i < NN) ? g_cnt[i] : 0;
    sh[tid] = v;
    __syncthreads();
#pragma unroll
    for (int off = 1; off < 256; off <<= 1) {
        int u = 0;
        if (tid >= off) u = sh[tid - off];
        __syncthreads();
        if (tid >= off) sh[tid] += u;
        __syncthreads();
    }
    if (tid == 255) sbase = atomicAdd(&g_total, sh[255]);
    __syncthreads();
    if (i < NN) {
        int start = sbase + sh[tid] - v;
        g_off[i]  = start;
        g_kcur[i] = start;
    }
}

// ---------------- permute: payload sorted by dst ----------------
__global__ void k_permute(void) {
    int e = blockIdx.x * 256 + threadIdx.x;
    if (e >= EE) return;
    int d = __ldg(&g_edst[e]);
    int pos = atomicAdd(&g_kcur[d], 1);
    g_sedge[pos] = __ldg(&g_pack[e]);
}

// ---------------- segmented sum: out[d] = relu(sum_e y[pack_e] + b) --------
// half-warp (16 lanes = 16 float4 cols) per dst; 8-way unrolled gathers.
__global__ void __launch_bounds__(256) k_segsum(const float* __restrict__ y,
                                                const float* __restrict__ bias,
                                                float* __restrict__ out) {
    int tid = threadIdx.x;
    int warpid = tid >> 5, lane = tid & 31;
    int eh = lane >> 4;
    int li = lane & 15;
    int d = blockIdx.x * 16 + warpid * 2 + eh;
    if (d >= NN) return;

    int start = __ldg(&g_off[d]);
    int cnt   = __ldg(&g_cnt[d]);
    const int* se = g_sedge + start;
    const float4* yv = (const float4*)y;

    float4 a0 = make_float4(0.f, 0.f, 0.f, 0.f);
    float4 a1 = a0, a2 = a0, a3 = a0;
    float4 a4 = a0, a5 = a0, a6 = a0, a7 = a0;

    int e = 0;
    for (; e + 8 <= cnt; e += 8) {
        int i0 = __ldg(se + e);
        int i1 = __ldg(se + e + 1);
        int i2 = __ldg(se + e + 2);
        int i3 = __ldg(se + e + 3);
        int i4 = __ldg(se + e + 4);
        int i5 = __ldg(se + e + 5);
        int i6 = __ldg(se + e + 6);
        int i7 = __ldg(se + e + 7);
        float4 v0 = __ldg(&yv[(size_t)i0 * 16 + li]);
        float4 v1 = __ldg(&yv[(size_t)i1 * 16 + li]);
        float4 v2 = __ldg(&yv[(size_t)i2 * 16 + li]);
        float4 v3 = __ldg(&yv[(size_t)i3 * 16 + li]);
        float4 v4 = __ldg(&yv[(size_t)i4 * 16 + li]);
        float4 v5 = __ldg(&yv[(size_t)i5 * 16 + li]);
        float4 v6 = __ldg(&yv[(size_t)i6 * 16 + li]);
        float4 v7 = __ldg(&yv[(size_t)i7 * 16 + li]);
        a0.x += v0.x; a0.y += v0.y; a0.z += v0.z; a0.w += v0.w;
        a1.x += v1.x; a1.y += v1.y; a1.z += v1.z; a1.w += v1.w;
        a2.x += v2.x; a2.y += v2.y; a2.z += v2.z; a2.w += v2.w;
        a3.x += v3.x; a3.y += v3.y; a3.z += v3.z; a3.w += v3.w;
        a4.x += v4.x; a4.y += v4.y; a4.z += v4.z; a4.w += v4.w;
        a5.x += v5.x; a5.y += v5.y; a5.z += v5.z; a5.w += v5.w;
        a6.x += v6.x; a6.y += v6.y; a6.z += v6.z; a6.w += v6.w;
        a7.x += v7.x; a7.y += v7.y; a7.z += v7.z; a7.w += v7.w;
    }
    for (; e < cnt; e++) {
        int i0 = __ldg(se + e);
        float4 v0 = __ldg(&yv[(size_t)i0 * 16 + li]);
        a0.x += v0.x; a0.y += v0.y; a0.z += v0.z; a0.w += v0.w;
    }

    a0.x += a1.x; a0.y += a1.y; a0.z += a1.z; a0.w += a1.w;
    a2.x += a3.x; a2.y += a3.y; a2.z += a3.z; a2.w += a3.w;
    a4.x += a5.x; a4.y += a5.y; a4.z += a5.z; a4.w += a5.w;
    a6.x += a7.x; a6.y += a7.y; a6.z += a7.z; a6.w += a7.w;
    a0.x += a2.x; a0.y += a2.y; a0.z += a2.z; a0.w += a2.w;
    a4.x += a6.x; a4.y += a6.y; a4.z += a6.z; a4.w += a6.w;
    a0.x += a4.x; a0.y += a4.y; a0.z += a4.z; a0.w += a4.w;

    float4 bv = __ldg(&((const float4*)bias)[li]);
    float4 r;
    r.x = fmaxf(a0.x + bv.x, 0.f);
    r.y = fmaxf(a0.y + bv.y, 0.f);
    r.z = fmaxf(a0.z + bv.z, 0.f);
    r.w = fmaxf(a0.w + bv.w, 0.f);
    ((float4*)out)[(size_t)d * 16 + li] = r;
}

// ---------------- ssl = h2 @ Wssl + bssl ----------------
__global__ void __launch_bounds__(256) k_ssl(const float* __restrict__ h2,
                                             const float* __restrict__ Wssl,
                                             const float* __restrict__ bssl,
                                             float* __restrict__ out) {
    __shared__ float ws[64 * 64];
    __shared__ float hs[4 * 64];
    int tid = threadIdx.x;
    int nb  = blockIdx.x * 4;

    {
        float4* wsv = (float4*)ws;
        const float4* Wv = (const float4*)Wssl;
#pragma unroll
        for (int k = 0; k < 4; k++) wsv[tid + k * 256] = Wv[tid + k * 256];
        hs[tid] = h2[(size_t)nb * 64 + tid];
    }
    __syncthreads();

    int nl = tid >> 6;
    int fo = tid & 63;
    float a = __ldg(&bssl[fo]);
#pragma unroll 8
    for (int fin = 0; fin < 64; ++fin)
        a += hs[nl * 64 + fin] * ws[fin * 64 + fo];
    out[(size_t)(nb + nl) * 64 + fo] = a;
}

// ---------------- launch: sort || gemm1 on two streams ----------------
extern "C" void kernel_launch(void* const* d_in, const int* in_sizes, int n_in,
                              void* d_out, int out_size) {
    const float* x    = (const float*)d_in[0];
    const void*  ei   = d_in[1];
    const void*  ti   = d_in[2];
    const float* W1   = (const float*)d_in[3];
    const float* b1   = (const float*)d_in[4];
    const float* W2   = (const float*)d_in[5];
    const float* b2   = (const float*)d_in[6];
    const float* Wssl = (const float*)d_in[7];
    const float* bssl = (const float*)d_in[8];
    float* out_h   = (float*)d_out;
    float* out_ssl = (float*)d_out + (size_t)NN * 64;

    float* dV1;  cudaGetSymbolAddress((void**)&dV1, g_V1);
    float* dV2;  cudaGetSymbolAddress((void**)&dV2, g_V2);
    float* dy;   cudaGetSymbolAddress((void**)&dy, g_y);
    float* dh1;  cudaGetSymbolAddress((void**)&dh1, g_h1);

    static cudaStream_t sA = 0;
    static cudaEvent_t evFork, evJoin;
    static int inited = 0;
    if (!inited) {
        cudaStreamCreateWithFlags(&sA, cudaStreamNonBlocking);
        cudaEventCreateWithFlags(&evFork, cudaEventDisableTiming);
        cudaEventCreateWithFlags(&evJoin, cudaEventDisableTiming);
        inited = 1;
    }

    // 1: init (mode detect + zero + W permutes) on main stream
    k_init<<<INIT_BLKS, 256>>>((const int*)ei, W1, W2);

    // fork: sort on stream A, gemm layer 1 on main stream (independent)
    cudaEventRecord(evFork, 0);
    cudaStreamWaitEvent(sA, evFork, 0);

    k_hist<<<EE / 256, 256, 0, sA>>>(ei, ti);
    k_scanA<<<INIT_BLKS, 256, 0, sA>>>();
    k_permute<<<EE / 256, 256, 0, sA>>>();
    cudaEventRecord(evJoin, sA);

    k_gemm<<<NN / 16, 128>>>(x, dV1, dy);

    // join: segsum needs both gemm1 (main) and sort (sA)
    cudaStreamWaitEvent(0, evJoin, 0);

    // layer 1 reduce, layer 2, ssl — serial chain on main stream
    k_segsum<<<(NN + 15) / 16, 256>>>(dy, b1, dh1);
    k_gemm<<<NN / 16, 128>>>(dh1, dV2, dy);
    k_segsum<<<(NN + 15) / 16, 256>>>(dy, b2, out_h);
    k_ssl<<<NN / 4, 256>>>(out_h, Wssl, bssl, out_ssl);
}

// round 12
// speedup vs baseline: 1.0004x; 1.0004x over previous
#include <cuda_runtime.h>
#include <stdint.h>

#define NN 100000
#define EE 3200000
#define TT 8
#define FF 64
#define NK (NN * TT)            // 800000 buckets, key = dst*8 + t
#define KBLKS (NK / 256)        // 3125
#define DPB 32                  // dsts per fused block
#define FUSED_SMEM (DPB * 520 * 4)   // 66560 B

// ---------------- device scratch (allocation-free) ----------------
__device__ float g_h1[(size_t)NN * FF];   // 25.6 MB
__device__ int   g_sedge[EE];             // src payload sorted by key
__device__ int   g_key[EE];               // cached key
__device__ int   g_psrc[EE];              // cached src
__device__ int   g_cnt[NK];
__device__ int   g_off[NK];
__device__ int   g_kcur[NK];
__device__ int   g_total;
__device__ int   g_mode;                  // 1 = int64 indices, 0 = int32

#define FMA2(acc, a, b) asm("fma.rn.f32x2 %0, %1, %2, %0;" : "+l"(acc) : "l"(a), "l"(b))
__device__ __forceinline__ unsigned long long dup2(float v) {
    unsigned long long r;
    unsigned int b = __float_as_uint(v);
    asm("mov.b64 %0, {%1, %1};" : "=l"(r) : "r"(b));
    return r;
}
__device__ __forceinline__ float2 unpack2(unsigned long long v) {
    unsigned int lo, hi;
    asm("mov.b64 {%0, %1}, %2;" : "=r"(lo), "=r"(hi) : "l"(v));
    return make_float2(__uint_as_float(lo), __uint_as_float(hi));
}

// ---------------- init: zero counters + mode detect ----------------
__global__ void __launch_bounds__(256) k_init(const int* __restrict__ ei) {
    int i = blockIdx.x * 256 + threadIdx.x;
    if (i < NK) g_cnt[i] = 0;
    if (i == 0) g_total = 0;

    if (blockIdx.x == 0) {
        int v = ei[2 * threadIdx.x + 1];
        unsigned int ball = __ballot_sync(0xffffffffu, v != 0);
        __shared__ int nz[8];
        if ((threadIdx.x & 31) == 0) nz[threadIdx.x >> 5] = (ball != 0);
        __syncthreads();
        if (threadIdx.x == 0) {
            int any = 0;
            for (int w = 0; w < 8; w++) any |= nz[w];
            g_mode = any ? 0 : 1;
        }
    }
}

// ---------------- histogram over key = dst*8 + t (caches key & src) --------
__global__ void k_hist(const void* __restrict__ ei_raw, const void* __restrict__ ti_raw) {
    int e = blockIdx.x * 256 + threadIdx.x;
    if (e >= EE) return;
    int src, dst, t;
    if (g_mode) {
        const long long* ei = (const long long*)ei_raw;
        const long long* ti = (const long long*)ti_raw;
        src = (int)ei[e];
        dst = (int)ei[(size_t)EE + e];
        t   = (int)ti[e];
    } else {
        const int* ei = (const int*)ei_raw;
        const int* ti = (const int*)ti_raw;
        src = ei[e];
        dst = ei[EE + e];
        t   = ti[e];
    }
    int key = dst * TT + t;
    g_key[e] = key;
    g_psrc[e] = src;
    atomicAdd(&g_cnt[key], 1);
}

// ---------------- single-kernel ticketed scan over NK ----------------
__global__ void __launch_bounds__(256) k_scanA(void) {
    __shared__ int sh[256];
    __shared__ int sbase;
    int i = blockIdx.x * 256 + threadIdx.x;
    int tid = threadIdx.x;
    int v = g_cnt[i];
    sh[tid] = v;
    __syncthreads();
#pragma unroll
    for (int off = 1; off < 256; off <<= 1) {
        int u = 0;
        if (tid >= off) u = sh[tid - off];
        __syncthreads();
        if (tid >= off) sh[tid] += u;
        __syncthreads();
    }
    if (tid == 255) sbase = atomicAdd(&g_total, sh[255]);
    __syncthreads();
    int start = sbase + sh[tid] - v;
    g_off[i]  = start;
    g_kcur[i] = start;
}

// ---------------- permute: src payload sorted by key ----------------
__global__ void k_permute(void) {
    int e = blockIdx.x * 256 + threadIdx.x;
    if (e >= EE) return;
    int key = __ldg(&g_key[e]);
    int pos = atomicAdd(&g_kcur[key], 1);
    g_sedge[pos] = __ldg(&g_psrc[e]);
}

// ---------------- fused: CSR aggregate + register-blocked GEMM + bias+relu -
// 256 thr, 32 dsts. Phase A: half-warp (16 lanes) per dst, 2 dsts each,
// per-(dst,t) float4 accumulator, x gathers are L2-resident.
// Phase B: thread = 4 rows x 1 float4col x half-K; shfl-combine K halves.
__global__ void __launch_bounds__(256) k_fused(const float* __restrict__ in,
                                               const float* __restrict__ W,
                                               const float* __restrict__ bias,
                                               float* __restrict__ out) {
    extern __shared__ float xs[];          // [32][520]
    int tid = threadIdx.x;
    int nb = blockIdx.x * DPB;

    // ---- Phase A ----
    {
        int hw = tid >> 4;                 // 16 half-warps
        int li = tid & 15;                 // float4 column 0..15
        const float4* x4 = (const float4*)in;
#pragma unroll
        for (int p = 0; p < 2; p++) {
            int slot = hw * 2 + p;
            int d = nb + slot;
            const int4* offp = (const int4*)&g_off[d * TT];
            const int4* cntp = (const int4*)&g_cnt[d * TT];
            int4 o0 = __ldg(&offp[0]);
            int4 o1 = __ldg(&offp[1]);
            int4 c0 = __ldg(&cntp[0]);
            int4 c1 = __ldg(&cntp[1]);
            int st[8] = {o0.x, o0.y, o0.z, o0.w, o1.x, o1.y, o1.z, o1.w};
            int cn[8] = {c0.x, c0.y, c0.z, c0.w, c1.x, c1.y, c1.z, c1.w};
#pragma unroll
            for (int t = 0; t < TT; t++) {
                float4 acc = make_float4(0.f, 0.f, 0.f, 0.f);
                float4 acc2 = acc;
                int s = st[t], en = st[t] + cn[t];
                for (; s + 2 <= en; s += 2) {
                    int r0 = __ldg(&g_sedge[s]);
                    int r1 = __ldg(&g_sedge[s + 1]);
                    float4 v0 = __ldg(&x4[(size_t)r0 * 16 + li]);
                    float4 v1 = __ldg(&x4[(size_t)r1 * 16 + li]);
                    acc.x += v0.x; acc.y += v0.y; acc.z += v0.z; acc.w += v0.w;
                    acc2.x += v1.x; acc2.y += v1.y; acc2.z += v1.z; acc2.w += v1.w;
                }
                if (s < en) {
                    int r0 = __ldg(&g_sedge[s]);
                    float4 v0 = __ldg(&x4[(size_t)r0 * 16 + li]);
                    acc.x += v0.x; acc.y += v0.y; acc.z += v0.z; acc.w += v0.w;
                }
                acc.x += acc2.x; acc.y += acc2.y; acc.z += acc2.z; acc.w += acc2.w;
                *(float4*)&xs[slot * 520 + t * 64 + li * 4] = acc;
            }
        }
    }
    __syncthreads();

    // ---- Phase B ----
    int g    = tid >> 7;                   // half-block: rows g*16..g*16+15
    int t2   = tid & 127;
    int w    = t2 >> 5;                    // warp in half-block
    int lane = t2 & 31;
    int f4c  = lane & 15;                  // float4 output column
    int kh   = lane >> 4;                  // K half
    int row0 = g * 16 + w * 4;

    const ulonglong2* Wp = (const ulonglong2*)W;    // [512][16] float4 rows
    unsigned long long a0[4] = {0, 0, 0, 0};
    unsigned long long a1[4] = {0, 0, 0, 0};
    int finbase = kh << 8;                 // 0 or 256

#pragma unroll 4
    for (int q = 0; q < 64; q++) {
        int fin = finbase + q * 4;
        ulonglong2 w0 = __ldg(&Wp[(fin + 0) * 16 + f4c]);
        ulonglong2 w1 = __ldg(&Wp[(fin + 1) * 16 + f4c]);
        ulonglong2 w2 = __ldg(&Wp[(fin + 2) * 16 + f4c]);
        ulonglong2 w3 = __ldg(&Wp[(fin + 3) * 16 + f4c]);
#pragma unroll
        for (int r = 0; r < 4; r++) {
            float4 xv = *(const float4*)&xs[(row0 + r) * 520 + fin];
            unsigned long long x0 = dup2(xv.x), x1 = dup2(xv.y);
            unsigned long long x2 = dup2(xv.z), x3 = dup2(xv.w);
            FMA2(a0[r], x0, w0.x); FMA2(a1[r], x0, w0.y);
            FMA2(a0[r], x1, w1.x); FMA2(a1[r], x1, w1.y);
            FMA2(a0[r], x2, w2.x); FMA2(a1[r], x2, w2.y);
            FMA2(a0[r], x3, w3.x); FMA2(a1[r], x3, w3.y);
        }
    }

    // combine K halves (lane L += lane L+16), bias, relu, store
    float4 bv = __ldg(&((const float4*)bias)[f4c]);
#pragma unroll
    for (int r = 0; r < 4; r++) {
        unsigned long long b0 = __shfl_down_sync(0xffffffffu, a0[r], 16);
        unsigned long long b1 = __shfl_down_sync(0xffffffffu, a1[r], 16);
        if (kh == 0) {
            float2 p0 = unpack2(a0[r]), q0 = unpack2(b0);
            float2 p1 = unpack2(a1[r]), q1 = unpack2(b1);
            float4 rr;
            rr.x = fmaxf(p0.x + q0.x + bv.x, 0.f);
            rr.y = fmaxf(p0.y + q0.y + bv.y, 0.f);
            rr.z = fmaxf(p1.x + q1.x + bv.z, 0.f);
            rr.w = fmaxf(p1.y + q1.y + bv.w, 0.f);
            ((float4*)out)[(size_t)(nb + row0 + r) * 16 + f4c] = rr;
        }
    }
}

// ---------------- ssl = h2 @ Wssl + bssl ----------------
__global__ void __launch_bounds__(256) k_ssl(const float* __restrict__ h2,
                                             const float* __restrict__ Wssl,
                                             const float* __restrict__ bssl,
                                             float* __restrict__ out) {
    __shared__ float ws[64 * 64];
    __shared__ float hs[4 * 64];
    int tid = threadIdx.x;
    int nb  = blockIdx.x * 4;

    {
        float4* wsv = (float4*)ws;
        const float4* Wv = (const float4*)Wssl;
#pragma unroll
        for (int k = 0; k < 4; k++) wsv[tid + k * 256] = Wv[tid + k * 256];
        hs[tid] = h2[(size_t)nb * 64 + tid];
    }
    __syncthreads();

    int nl = tid >> 6;
    int fo = tid & 63;
    float a = __ldg(&bssl[fo]);
#pragma unroll 8
    for (int fin = 0; fin < 64; ++fin)
        a += hs[nl * 64 + fin] * ws[fin * 64 + fo];
    out[(size_t)(nb + nl) * 64 + fo] = a;
}

// ---------------- launch (serial; overlap hurt in R11) ----------------
extern "C" void kernel_launch(void* const* d_in, const int* in_sizes, int n_in,
                              void* d_out, int out_size) {
    const float* x    = (const float*)d_in[0];
    const void*  ei   = d_in[1];
    const void*  ti   = d_in[2];
    const float* W1   = (const float*)d_in[3];
    const float* b1   = (const float*)d_in[4];
    const float* W2   = (const float*)d_in[5];
    const float* b2   = (const float*)d_in[6];
    const float* Wssl = (const float*)d_in[7];
    const float* bssl = (const float*)d_in[8];
    float* out_h   = (float*)d_out;
    float* out_ssl = (float*)d_out + (size_t)NN * 64;

    float* dh1;  cudaGetSymbolAddress((void**)&dh1, g_h1);

    static int smem_set = 0;
    if (!smem_set) {
        cudaFuncSetAttribute(k_fused, cudaFuncAttributeMaxDynamicSharedMemorySize,
                             FUSED_SMEM);
        smem_set = 1;
    }

    // 1-4: counting sort by (dst*8+t)
    k_init<<<KBLKS, 256>>>((const int*)ei);
    k_hist<<<EE / 256, 256>>>(ei, ti);
    k_scanA<<<KBLKS, 256>>>();
    k_permute<<<EE / 256, 256>>>();

    // 5-6: fused layers (no atomics, no y intermediate)
    k_fused<<<NN / DPB, 256, FUSED_SMEM>>>(x, W1, b1, dh1);
    k_fused<<<NN / DPB, 256, FUSED_SMEM>>>(dh1, W2, b2, out_h);

    // 7: ssl head
    k_ssl<<<NN / 4, 256>>>(out_h, Wssl, bssl, out_ssl);
}

// round 13
// speedup vs baseline: 1.3100x; 1.3094x over previous
#include <cuda_runtime.h>
#include <cuda_fp16.h>
#include <stdint.h>

#define NN 100000
#define EE 3200000
#define TT 8
#define FF 64
#define INIT_BLKS 391           // ceil(NN/256)

// ---------------- device scratch (allocation-free) ----------------
__device__ __half g_y[(size_t)TT * NN * FF];  // 102.4 MB: y[t*N+n][f] (fp16)
__device__ float g_h1[(size_t)NN * FF];       // 25.6 MB
__device__ float g_V1[64 * 512];              // permuted W1: V[fin][t*64+fout]
__device__ float g_V2[64 * 512];
__device__ int   g_pack[EE];                  // t*NN + src (payload)
__device__ int   g_edst[EE];                  // dst (sort key)
__device__ int   g_sedge[EE];                 // payload sorted by dst
__device__ int   g_cnt[NN];
__device__ int   g_off[NN];
__device__ int   g_kcur[NN];
__device__ int   g_total;
__device__ int   g_mode;                      // 1 = int64 indices, 0 = int32

#define FMA2(acc, a, b) asm("fma.rn.f32x2 %0, %1, %2, %0;" : "+l"(acc) : "l"(a), "l"(b))
__device__ __forceinline__ float2 unpack2(unsigned long long v) {
    unsigned int lo, hi;
    asm("mov.b64 {%0, %1}, %2;" : "=r"(lo), "=r"(hi) : "l"(v));
    return make_float2(__uint_as_float(lo), __uint_as_float(hi));
}

// ---------------- init: mode detect + zero counters + permute W1/W2 --------
__global__ void __launch_bounds__(256) k_init(const int* __restrict__ ei,
                                              const float* __restrict__ W1,
                                              const float* __restrict__ W2) {
    int i = blockIdx.x * 256 + threadIdx.x;
    if (i < NN) g_cnt[i] = 0;
    if (i == 0) g_total = 0;

    if (i < 32768) {
        int fin = i >> 9;
        int j   = i & 511;
        int t   = j >> 6;
        int fo  = j & 63;
        g_V1[i] = W1[((t << 6) + fin) * 64 + fo];
        g_V2[i] = W2[((t << 6) + fin) * 64 + fo];
    }

    if (blockIdx.x == 0) {
        int v = ei[2 * threadIdx.x + 1];
        unsigned int ball = __ballot_sync(0xffffffffu, v != 0);
        __shared__ int nz[8];
        if ((threadIdx.x & 31) == 0) nz[threadIdx.x >> 5] = (ball != 0);
        __syncthreads();
        if (threadIdx.x == 0) {
            int any = 0;
            for (int w = 0; w < 8; w++) any |= nz[w];
            g_mode = any ? 0 : 1;
        }
    }
}

// ---------------- y[t*N+n][:] = in[n][:] @ W_t  (f32x2 FMA, fp16 store) ----
__global__ void __launch_bounds__(128) k_gemm(const float* __restrict__ in,
                                              const float* __restrict__ V,
                                              __half* __restrict__ y) {
    __shared__ float xs[16][64];
    int tid = threadIdx.x;
    int nb  = blockIdx.x * 16;

    {
        const float4* inv = (const float4*)(in + (size_t)nb * 64);
        float4* xsv = (float4*)&xs[0][0];
        xsv[tid]       = inv[tid];
        xsv[tid + 128] = inv[tid + 128];
    }
    __syncthreads();

    int jt = tid & 31;
    int ng = tid >> 5;

    unsigned long long acc[4][4][2];
#pragma unroll
    for (int i = 0; i < 4; i++)
#pragma unroll
        for (int s = 0; s < 4; s++) { acc[i][s][0] = 0ull; acc[i][s][1] = 0ull; }

    const ulonglong2* Vr = (const ulonglong2*)V;

#pragma unroll 4
    for (int fin = 0; fin < 64; ++fin) {
        unsigned long long xv[4];
#pragma unroll
        for (int i = 0; i < 4; i++) {
            unsigned int xb = __float_as_uint(xs[(ng << 2) + i][fin]);
            asm("mov.b64 %0, {%1, %1};" : "=l"(xv[i]) : "r"(xb));
        }
#pragma unroll
        for (int s = 0; s < 4; s++) {
            ulonglong2 w = __ldg(&Vr[fin * 128 + jt + s * 32]);
#pragma unroll
            for (int i = 0; i < 4; i++) {
                FMA2(acc[i][s][0], xv[i], w.x);
                FMA2(acc[i][s][1], xv[i], w.y);
            }
        }
    }

    uint2* yv = (uint2*)y;                    // 4 halfs per element
#pragma unroll
    for (int s = 0; s < 4; s++) {
        int j4 = jt + s * 32;
        int t  = j4 >> 4;
        int c4 = j4 & 15;
#pragma unroll
        for (int i = 0; i < 4; i++) {
            int node = nb + (ng << 2) + i;
            float2 f0 = unpack2(acc[i][s][0]);
            float2 f1 = unpack2(acc[i][s][1]);
            __half2 h0 = __float22half2_rn(f0);
            __half2 h1 = __float22half2_rn(f1);
            uint2 o;
            o.x = *(unsigned int*)&h0;
            o.y = *(unsigned int*)&h1;
            yv[(size_t)(t * NN + node) * 16 + c4] = o;
        }
    }
}

// ---------------- histogram over dst (caches key & payload) ----------------
__global__ void k_hist(const void* __restrict__ ei_raw, const void* __restrict__ ti_raw) {
    int e = blockIdx.x * 256 + threadIdx.x;
    if (e >= EE) return;
    int src, dst, t;
    if (g_mode) {
        const long long* ei = (const long long*)ei_raw;
        const long long* ti = (const long long*)ti_raw;
        src = (int)ei[e];
        dst = (int)ei[(size_t)EE + e];
        t   = (int)ti[e];
    } else {
        const int* ei = (const int*)ei_raw;
        const int* ti = (const int*)ti_raw;
        src = ei[e];
        dst = ei[EE + e];
        t   = ti[e];
    }
    g_pack[e] = t * NN + src;
    g_edst[e] = dst;
    atomicAdd(&g_cnt[dst], 1);
}

// ---------------- single-kernel ticketed scan ----------------
__global__ void __launch_bounds__(256) k_scanA(void) {
    __shared__ int sh[256];
    __shared__ int sbase;
    int i = blockIdx.x * 256 + threadIdx.x;
    int tid = threadIdx.x;
    int v = (i < NN) ? g_cnt[i] : 0;
    sh[tid] = v;
    __syncthreads();
#pragma unroll
    for (int off = 1; off < 256; off <<= 1) {
        int u = 0;
        if (tid >= off) u = sh[tid - off];
        __syncthreads();
        if (tid >= off) sh[tid] += u;
        __syncthreads();
    }
    if (tid == 255) sbase = atomicAdd(&g_total, sh[255]);
    __syncthreads();
    if (i < NN) {
        int start = sbase + sh[tid] - v;
        g_off[i]  = start;
        g_kcur[i] = start;
    }
}

// ---------------- permute: payload sorted by dst ----------------
__global__ void k_permute(void) {
    int e = blockIdx.x * 256 + threadIdx.x;
    if (e >= EE) return;
    int d = __ldg(&g_edst[e]);
    int pos = atomicAdd(&g_kcur[d], 1);
    g_sedge[pos] = __ldg(&g_pack[e]);
}

// ---------------- segmented sum: out[d] = relu(sum_e y[pack_e] + b) --------
// half-warp (16 lanes x 4 halfs = 64 cols) per dst; 4-way unrolled gathers.
__global__ void __launch_bounds__(256) k_segsum(const __half* __restrict__ y,
                                                const float* __restrict__ bias,
                                                float* __restrict__ out) {
    int tid = threadIdx.x;
    int warpid = tid >> 5, lane = tid & 31;
    int eh = lane >> 4;
    int li = lane & 15;
    int d = blockIdx.x * 16 + warpid * 2 + eh;
    if (d >= NN) return;

    int start = __ldg(&g_off[d]);
    int cnt   = __ldg(&g_cnt[d]);
    const int* se = g_sedge + start;
    const uint2* yv = (const uint2*)y;

    float4 a0 = make_float4(0.f, 0.f, 0.f, 0.f);
    float4 a1 = a0, a2 = a0, a3 = a0;

    int e = 0;
    for (; e + 4 <= cnt; e += 4) {
        int i0 = __ldg(se + e);
        int i1 = __ldg(se + e + 1);
        int i2 = __ldg(se + e + 2);
        int i3 = __ldg(se + e + 3);
        uint2 u0 = __ldg(&yv[(size_t)i0 * 16 + li]);
        uint2 u1 = __ldg(&yv[(size_t)i1 * 16 + li]);
        uint2 u2 = __ldg(&yv[(size_t)i2 * 16 + li]);
        uint2 u3 = __ldg(&yv[(size_t)i3 * 16 + li]);
        float2 p, q;
        p = __half22float2(*(__half2*)&u0.x); q = __half22float2(*(__half2*)&u0.y);
        a0.x += p.x; a0.y += p.y; a0.z += q.x; a0.w += q.y;
        p = __half22float2(*(__half2*)&u1.x); q = __half22float2(*(__half2*)&u1.y);
        a1.x += p.x; a1.y += p.y; a1.z += q.x; a1.w += q.y;
        p = __half22float2(*(__half2*)&u2.x); q = __half22float2(*(__half2*)&u2.y);
        a2.x += p.x; a2.y += p.y; a2.z += q.x; a2.w += q.y;
        p = __half22float2(*(__half2*)&u3.x); q = __half22float2(*(__half2*)&u3.y);
        a3.x += p.x; a3.y += p.y; a3.z += q.x; a3.w += q.y;
    }
    for (; e < cnt; e++) {
        int i0 = __ldg(se + e);
        uint2 u0 = __ldg(&yv[(size_t)i0 * 16 + li]);
        float2 p = __half22float2(*(__half2*)&u0.x);
        float2 q = __half22float2(*(__half2*)&u0.y);
        a0.x += p.x; a0.y += p.y; a0.z += q.x; a0.w += q.y;
    }

    a0.x += a1.x + a2.x + a3.x;
    a0.y += a1.y + a2.y + a3.y;
    a0.z += a1.z + a2.z + a3.z;
    a0.w += a1.w + a2.w + a3.w;

    // bias: this lane covers output cols li*4 .. li*4+3
    float4 bv = __ldg(&((const float4*)bias)[li]);
    float4 r;
    r.x = fmaxf(a0.x + bv.x, 0.f);
    r.y = fmaxf(a0.y + bv.y, 0.f);
    r.z = fmaxf(a0.z + bv.z, 0.f);
    r.w = fmaxf(a0.w + bv.w, 0.f);
    ((float4*)out)[(size_t)d * 16 + li] = r;
}

// ---------------- ssl = h2 @ Wssl + bssl ----------------
__global__ void __launch_bounds__(256) k_ssl(const float* __restrict__ h2,
                                             const float* __restrict__ Wssl,
                                             const float* __restrict__ bssl,
                                             float* __restrict__ out) {
    __shared__ float ws[64 * 64];
    __shared__ float hs[4 * 64];
    int tid = threadIdx.x;
    int nb  = blockIdx.x * 4;

    {
        float4* wsv = (float4*)ws;
        const float4* Wv = (const float4*)Wssl;
#pragma unroll
        for (int k = 0; k < 4; k++) wsv[tid + k * 256] = Wv[tid + k * 256];
        hs[tid] = h2[(size_t)nb * 64 + tid];
    }
    __syncthreads();

    int nl = tid >> 6;
    int fo = tid & 63;
    float a = __ldg(&bssl[fo]);
#pragma unroll 8
    for (int fin = 0; fin < 64; ++fin)
        a += hs[nl * 64 + fin] * ws[fin * 64 + fo];
    out[(size_t)(nb + nl) * 64 + fo] = a;
}

// ---------------- launch (serial, R10 order) ----------------
extern "C" void kernel_launch(void* const* d_in, const int* in_sizes, int n_in,
                              void* d_out, int out_size) {
    const float* x    = (const float*)d_in[0];
    const void*  ei   = d_in[1];
    const void*  ti   = d_in[2];
    const float* W1   = (const float*)d_in[3];
    const float* b1   = (const float*)d_in[4];
    const float* W2   = (const float*)d_in[5];
    const float* b2   = (const float*)d_in[6];
    const float* Wssl = (const float*)d_in[7];
    const float* bssl = (const float*)d_in[8];
    float* out_h   = (float*)d_out;
    float* out_ssl = (float*)d_out + (size_t)NN * 64;

    float* dV1;  cudaGetSymbolAddress((void**)&dV1, g_V1);
    float* dV2;  cudaGetSymbolAddress((void**)&dV2, g_V2);
    __half* dy;  cudaGetSymbolAddress((void**)&dy, g_y);
    float* dh1;  cudaGetSymbolAddress((void**)&dh1, g_h1);

    // 1: init (mode detect + zero + W permutes)
    k_init<<<INIT_BLKS, 256>>>((const int*)ei, W1, W2);
    // 2: gemm layer 1
    k_gemm<<<NN / 16, 128>>>(x, dV1, dy);
    // 3-5: counting sort by dst
    k_hist<<<EE / 256, 256>>>(ei, ti);
    k_scanA<<<INIT_BLKS, 256>>>();
    k_permute<<<EE / 256, 256>>>();
    // 6: segmented sum layer 1
    k_segsum<<<(NN + 15) / 16, 256>>>(dy, b1, dh1);
    // 7-8: layer 2
    k_gemm<<<NN / 16, 128>>>(dh1, dV2, dy);
    k_segsum<<<(NN + 15) / 16, 256>>>(dy, b2, out_h);
    // 9: ssl head
    k_ssl<<<NN / 4, 256>>>(out_h, Wssl, bssl, out_ssl);
}

// round 14
// speedup vs baseline: 1.7479x; 1.3343x over previous
#include <cuda_runtime.h>
#include <cuda_fp16.h>
#include <stdint.h>

#define NN 100000
#define EE 3200000
#define TT 8
#define FF 64
#define INIT_BLKS 391           // ceil(NN/256)

// ---------------- device scratch (allocation-free) ----------------
__device__ __half g_y[(size_t)TT * NN * FF];  // 102.4 MB: y[t*N+n][f] (fp16)
__device__ float g_h1[(size_t)NN * FF];       // 25.6 MB
__device__ unsigned int g_Vf1[16384];         // W1 fp16, mma-fragment order
__device__ unsigned int g_Vf2[16384];         // W2 fp16, mma-fragment order
__device__ int   g_pack[EE];                  // t*NN + src (payload)
__device__ int   g_edst[EE];                  // dst (sort key)
__device__ int   g_sedge[EE];                 // payload sorted by dst
__device__ int   g_cnt[NN];
__device__ int   g_off[NN];
__device__ int   g_kcur[NN];
__device__ int   g_total;
__device__ int   g_mode;                      // 1 = int64 indices, 0 = int32

// ---------------- init: mode detect + zero + W->fp16 fragment pack ---------
// fragment uint i: p=i&1, l=(i>>1)&31, nn=(i>>6)&63, kk=(i>>12)&3
//   k1 = kk*16 + (l&3)*2 + p*8 ; n1 = nn*8 + (l>>2)
//   value = half2( W[((n1>>6)*64 + k1)*64 + (n1&63)],
//                  W[((n1>>6)*64 + k1 + 1)*64 + (n1&63)] )
__global__ void __launch_bounds__(256) k_init(const int* __restrict__ ei,
                                              const float* __restrict__ W1,
                                              const float* __restrict__ W2) {
    int i = blockIdx.x * 256 + threadIdx.x;
    if (i < NN) g_cnt[i] = 0;
    if (i == 0) g_total = 0;

    if (i < 32768) {
        int fi = i & 16383;
        const float* W = (i < 16384) ? W1 : W2;
        int p  = fi & 1;
        int l  = (fi >> 1) & 31;
        int nn = (fi >> 6) & 63;
        int kk = (fi >> 12) & 3;
        int k1 = kk * 16 + (l & 3) * 2 + p * 8;
        int n1 = nn * 8 + (l >> 2);
        int row = (n1 >> 6) * 64 + k1;
        float e0 = __ldg(&W[row * 64 + (n1 & 63)]);
        float e1 = __ldg(&W[(row + 1) * 64 + (n1 & 63)]);
        __half2 hv = __floats2half2_rn(e0, e1);
        unsigned int u = *(unsigned int*)&hv;
        if (i < 16384) g_Vf1[fi] = u; else g_Vf2[fi] = u;
    }

    if (blockIdx.x == 0) {
        int v = ei[2 * threadIdx.x + 1];
        unsigned int ball = __ballot_sync(0xffffffffu, v != 0);
        __shared__ int nz[8];
        if ((threadIdx.x & 31) == 0) nz[threadIdx.x >> 5] = (ball != 0);
        __syncthreads();
        if (threadIdx.x == 0) {
            int any = 0;
            for (int w = 0; w < 8; w++) any |= nz[w];
            g_mode = any ? 0 : 1;
        }
    }
}

// ---------------- HMMA gemm: y[t*N+n][fo] = x[n][:] @ W_t ------------------
// block = 32 nodes, 256 thr = 8 warps; warp = 16 rows x 128 cols (16 tiles).
// A: fp32->fp16 smem, padded stride 72 halfs (conflict-free LDS.32 a-frags).
// B: fragment-ordered fp16 from global (64KB, L1-resident), LDG.64 per tile.
__global__ void __launch_bounds__(256) k_gemm(const float* __restrict__ in,
                                              const unsigned int* __restrict__ Vf,
                                              __half* __restrict__ y) {
    __shared__ __half As[32 * 72];
    int tid = threadIdx.x;
    int nb  = blockIdx.x * 32;

    // stage x tile fp32 -> fp16 (32 rows x 64 cols)
    {
        int row = tid >> 3, seg = tid & 7;
        const float4* xr = (const float4*)(in + (size_t)(nb + row) * 64 + seg * 8);
        float4 f0 = __ldg(&xr[0]);
        float4 f1 = __ldg(&xr[1]);
        __half2 h0 = __floats2half2_rn(f0.x, f0.y);
        __half2 h1 = __floats2half2_rn(f0.z, f0.w);
        __half2 h2 = __floats2half2_rn(f1.x, f1.y);
        __half2 h3 = __floats2half2_rn(f1.z, f1.w);
        uint4 u;
        u.x = *(unsigned int*)&h0; u.y = *(unsigned int*)&h1;
        u.z = *(unsigned int*)&h2; u.w = *(unsigned int*)&h3;
        *(uint4*)&As[row * 72 + seg * 8] = u;
    }
    __syncthreads();

    int warpid = tid >> 5, lane = tid & 31;
    int rg = warpid >> 2;              // row group: rows rg*16..+15
    int cq = warpid & 3;               // col quarter: n-tiles cq*16..+15
    int m0 = rg * 16;
    int gr = lane >> 2;                // 0..7
    int kc2 = (lane & 3);              // kc = kc2*2

    float d[16][4];
#pragma unroll
    for (int q = 0; q < 16; q++) { d[q][0] = 0.f; d[q][1] = 0.f; d[q][2] = 0.f; d[q][3] = 0.f; }

    const unsigned int* As32 = (const unsigned int*)As;
    const uint2* Bf = (const uint2*)Vf;      // [(kk*64+nn)*32 + lane]

#pragma unroll
    for (int kk = 0; kk < 4; kk++) {
        int kw = kk * 8 + kc2;               // word offset of kc within row
        unsigned int a0 = As32[(m0 + gr) * 36 + kw];
        unsigned int a1 = As32[(m0 + gr + 8) * 36 + kw];
        unsigned int a2 = As32[(m0 + gr) * 36 + kw + 4];
        unsigned int a3 = As32[(m0 + gr + 8) * 36 + kw + 4];
#pragma unroll
        for (int q = 0; q < 16; q++) {
            int nn = cq * 16 + q;
            uint2 b = __ldg(&Bf[(kk * 64 + nn) * 32 + lane]);
            asm volatile(
                "mma.sync.aligned.m16n8k16.row.col.f32.f16.f16.f32 "
                "{%0,%1,%2,%3}, {%4,%5,%6,%7}, {%8,%9}, {%0,%1,%2,%3};"
                : "+f"(d[q][0]), "+f"(d[q][1]), "+f"(d[q][2]), "+f"(d[q][3])
                : "r"(a0), "r"(a1), "r"(a2), "r"(a3), "r"(b.x), "r"(b.y));
        }
    }

    // epilogue: d -> fp16 y.  tile nn covers global cols nn*8..+7 (one t each)
    __half2* y2 = (__half2*)y;
#pragma unroll
    for (int q = 0; q < 16; q++) {
        int nn = cq * 16 + q;
        int t  = nn >> 3;
        int jc = (nn & 7) * 8 + (lane & 3) * 2;   // col within 64, even
        int r0 = m0 + (lane >> 2);
        size_t base0 = ((size_t)t * NN + nb + r0) * 32 + (jc >> 1);
        size_t base1 = base0 + (size_t)8 * 32;    // row +8
        y2[base0] = __floats2half2_rn(d[q][0], d[q][1]);
        y2[base1] = __floats2half2_rn(d[q][2], d[q][3]);
    }
}

// ---------------- histogram over dst (caches key & payload) ----------------
__global__ void k_hist(const void* __restrict__ ei_raw, const void* __restrict__ ti_raw) {
    int e = blockIdx.x * 256 + threadIdx.x;
    if (e >= EE) return;
    int src, dst, t;
    if (g_mode) {
        const long long* ei = (const long long*)ei_raw;
        const long long* ti = (const long long*)ti_raw;
        src = (int)ei[e];
        dst = (int)ei[(size_t)EE + e];
        t   = (int)ti[e];
    } else {
        const int* ei = (const int*)ei_raw;
        const int* ti = (const int*)ti_raw;
        src = ei[e];
        dst = ei[EE + e];
        t   = ti[e];
    }
    g_pack[e] = t * NN + src;
    g_edst[e] = dst;
    atomicAdd(&g_cnt[dst], 1);
}

// ---------------- single-kernel ticketed scan ----------------
__global__ void __launch_bounds__(256) k_scanA(void) {
    __shared__ int sh[256];
    __shared__ int sbase;
    int i = blockIdx.x * 256 + threadIdx.x;
    int tid = threadIdx.x;
    int v = (i < NN) ? g_cnt[i] : 0;
    sh[tid] = v;
    __syncthreads();
#pragma unroll
    for (int off = 1; off < 256; off <<= 1) {
        int u = 0;
        if (tid >= off) u = sh[tid - off];
        __syncthreads();
        if (tid >= off) sh[tid] += u;
        __syncthreads();
    }
    if (tid == 255) sbase = atomicAdd(&g_total, sh[255]);
    __syncthreads();
    if (i < NN) {
        int start = sbase + sh[tid] - v;
        g_off[i]  = start;
        g_kcur[i] = start;
    }
}

// ---------------- permute: payload sorted by dst ----------------
__global__ void k_permute(void) {
    int e = blockIdx.x * 256 + threadIdx.x;
    if (e >= EE) return;
    int d = __ldg(&g_edst[e]);
    int pos = atomicAdd(&g_kcur[d], 1);
    g_sedge[pos] = __ldg(&g_pack[e]);
}

// ---------------- segmented sum: out[d] = relu(sum_e y[pack_e] + b) --------
__global__ void __launch_bounds__(256) k_segsum(const __half* __restrict__ y,
                                                const float* __restrict__ bias,
                                                float* __restrict__ out) {
    int tid = threadIdx.x;
    int warpid = tid >> 5, lane = tid & 31;
    int eh = lane >> 4;
    int li = lane & 15;
    int d = blockIdx.x * 16 + warpid * 2 + eh;
    if (d >= NN) return;

    int start = __ldg(&g_off[d]);
    int cnt   = __ldg(&g_cnt[d]);
    const int* se = g_sedge + start;
    const uint2* yv = (const uint2*)y;

    float4 a0 = make_float4(0.f, 0.f, 0.f, 0.f);
    float4 a1 = a0, a2 = a0, a3 = a0;

    int e = 0;
    for (; e + 4 <= cnt; e += 4) {
        int i0 = __ldg(se + e);
        int i1 = __ldg(se + e + 1);
        int i2 = __ldg(se + e + 2);
        int i3 = __ldg(se + e + 3);
        uint2 u0 = __ldg(&yv[(size_t)i0 * 16 + li]);
        uint2 u1 = __ldg(&yv[(size_t)i1 * 16 + li]);
        uint2 u2 = __ldg(&yv[(size_t)i2 * 16 + li]);
        uint2 u3 = __ldg(&yv[(size_t)i3 * 16 + li]);
        float2 p, q;
        p = __half22float2(*(__half2*)&u0.x); q = __half22float2(*(__half2*)&u0.y);
        a0.x += p.x; a0.y += p.y; a0.z += q.x; a0.w += q.y;
        p = __half22float2(*(__half2*)&u1.x); q = __half22float2(*(__half2*)&u1.y);
        a1.x += p.x; a1.y += p.y; a1.z += q.x; a1.w += q.y;
        p = __half22float2(*(__half2*)&u2.x); q = __half22float2(*(__half2*)&u2.y);
        a2.x += p.x; a2.y += p.y; a2.z += q.x; a2.w += q.y;
        p = __half22float2(*(__half2*)&u3.x); q = __half22float2(*(__half2*)&u3.y);
        a3.x += p.x; a3.y += p.y; a3.z += q.x; a3.w += q.y;
    }
    for (; e < cnt; e++) {
        int i0 = __ldg(se + e);
        uint2 u0 = __ldg(&yv[(size_t)i0 * 16 + li]);
        float2 p = __half22float2(*(__half2*)&u0.x);
        float2 q = __half22float2(*(__half2*)&u0.y);
        a0.x += p.x; a0.y += p.y; a0.z += q.x; a0.w += q.y;
    }

    a0.x += a1.x + a2.x + a3.x;
    a0.y += a1.y + a2.y + a3.y;
    a0.z += a1.z + a2.z + a3.z;
    a0.w += a1.w + a2.w + a3.w;

    float4 bv = __ldg(&((const float4*)bias)[li]);
    float4 r;
    r.x = fmaxf(a0.x + bv.x, 0.f);
    r.y = fmaxf(a0.y + bv.y, 0.f);
    r.z = fmaxf(a0.z + bv.z, 0.f);
    r.w = fmaxf(a0.w + bv.w, 0.f);
    ((float4*)out)[(size_t)d * 16 + li] = r;
}

// ---------------- ssl = h2 @ Wssl + bssl ----------------
__global__ void __launch_bounds__(256) k_ssl(const float* __restrict__ h2,
                                             const float* __restrict__ Wssl,
                                             const float* __restrict__ bssl,
                                             float* __restrict__ out) {
    __shared__ float ws[64 * 64];
    __shared__ float hs[4 * 64];
    int tid = threadIdx.x;
    int nb  = blockIdx.x * 4;

    {
        float4* wsv = (float4*)ws;
        const float4* Wv = (const float4*)Wssl;
#pragma unroll
        for (int k = 0; k < 4; k++) wsv[tid + k * 256] = Wv[tid + k * 256];
        hs[tid] = h2[(size_t)nb * 64 + tid];
    }
    __syncthreads();

    int nl = tid >> 6;
    int fo = tid & 63;
    float a = __ldg(&bssl[fo]);
#pragma unroll 8
    for (int fin = 0; fin < 64; ++fin)
        a += hs[nl * 64 + fin] * ws[fin * 64 + fo];
    out[(size_t)(nb + nl) * 64 + fo] = a;
}

// ---------------- launch (serial, champion order) ----------------
extern "C" void kernel_launch(void* const* d_in, const int* in_sizes, int n_in,
                              void* d_out, int out_size) {
    const float* x    = (const float*)d_in[0];
    const void*  ei   = d_in[1];
    const void*  ti   = d_in[2];
    const float* W1   = (const float*)d_in[3];
    const float* b1   = (const float*)d_in[4];
    const float* W2   = (const float*)d_in[5];
    const float* b2   = (const float*)d_in[6];
    const float* Wssl = (const float*)d_in[7];
    const float* bssl = (const float*)d_in[8];
    float* out_h   = (float*)d_out;
    float* out_ssl = (float*)d_out + (size_t)NN * 64;

    unsigned int* dVf1; cudaGetSymbolAddress((void**)&dVf1, g_Vf1);
    unsigned int* dVf2; cudaGetSymbolAddress((void**)&dVf2, g_Vf2);
    __half* dy;  cudaGetSymbolAddress((void**)&dy, g_y);
    float* dh1;  cudaGetSymbolAddress((void**)&dh1, g_h1);

    // 1: init (mode detect + zero + W fragment pack)
    k_init<<<INIT_BLKS, 256>>>((const int*)ei, W1, W2);
    // 2: HMMA gemm layer 1
    k_gemm<<<NN / 32, 256>>>(x, dVf1, dy);
    // 3-5: counting sort by dst
    k_hist<<<EE / 256, 256>>>(ei, ti);
    k_scanA<<<INIT_BLKS, 256>>>();
    k_permute<<<EE / 256, 256>>>();
    // 6: segmented sum layer 1
    k_segsum<<<(NN + 15) / 16, 256>>>(dy, b1, dh1);
    // 7-8: layer 2
    k_gemm<<<NN / 32, 256>>>(dh1, dVf2, dy);
    k_segsum<<<(NN + 15) / 16, 256>>>(dy, b2, out_h);
    // 9: ssl head
    k_ssl<<<NN / 4, 256>>>(out_h, Wssl, bssl, out_ssl);
}